// round 2
// baseline (speedup 1.0000x reference)
#include <cuda_runtime.h>
#include <math.h>
#include <stdint.h>

#define LSEQ 1024
#define WDIM 300
#define PDIM 100
#define DIN0 400
#define HDIR 512
#define HID  1024
#define G4   2048      // 4*HDIR
#define NCD  64        // CTAs per direction in recurrence

// ---------------- scratch (static device globals; no runtime allocation) ----
__device__ float g_emb[LSEQ * DIN0];
__device__ float g_xp[2ull * LSEQ * G4];
__device__ float g_h0[LSEQ * HID];
__device__ float g_h1[LSEQ * HID];
__device__ float g_feat[2ull * LSEQ * 512];
__device__ float g_s[2 * LSEQ];
__device__ int   g_cnt[128];   // [0],[32]=layer0 fwd/bwd; [64],[96]=layer1

// ---------------- embedding gather + counter reset ------------------------
__global__ void embed_kernel(const int* __restrict__ wt, const int* __restrict__ pt,
                             const float* __restrict__ wemb, const float* __restrict__ pemb) {
    if (blockIdx.x == 0 && threadIdx.x == 0) {
        g_cnt[0] = 0; g_cnt[32] = 0; g_cnt[64] = 0; g_cnt[96] = 0;
    }
    int t = blockIdx.x;
    int w = wt[t], p = pt[t];
    for (int i = threadIdx.x; i < WDIM; i += blockDim.x)
        g_emb[t * DIN0 + i] = wemb[(size_t)w * WDIM + i];
    for (int i = threadIdx.x; i < PDIM; i += blockDim.x)
        g_emb[t * DIN0 + WDIM + i] = pemb[(size_t)p * PDIM + i];
}

// ---------------- C[M,N] = A[M,K] @ B[N,K]^T + bias[N] ---------------------
// 128x128 tile, BK=8, 256 threads, 8x8 microtile, double-buffered smem.
// blockIdx.z selects (B0,bias0,C0) or (B1,bias1,C1). Requires M%128==0,
// N%128==0, K%8==0, pointers 16B-aligned.
__global__ __launch_bounds__(256) void gemm128(
    const float* __restrict__ A,
    const float* __restrict__ B0, const float* __restrict__ bias0, float* __restrict__ C0,
    const float* __restrict__ B1, const float* __restrict__ bias1, float* __restrict__ C1,
    int M, int N, int K)
{
    const float* B = B0; const float* bias = bias0; float* C = C0;
    if (blockIdx.z) { B = B1; bias = bias1; C = C1; }

    __shared__ float As[2][8][128];
    __shared__ float Bs[2][8][128];

    int tid = threadIdx.x;
    int m0 = blockIdx.y * 128, n0 = blockIdx.x * 128;
    int row = tid >> 1;           // 0..127
    int c4  = (tid & 1) * 4;      // 0 or 4
    int tx  = tid & 15, ty = tid >> 4;

    const float* Aptr = A + (size_t)(m0 + row) * K + c4;
    const float* Bptr = B + (size_t)(n0 + row) * K + c4;

    float4 a  = *(const float4*)Aptr;
    float4 bb = *(const float4*)Bptr;
    As[0][c4 + 0][row] = a.x;  As[0][c4 + 1][row] = a.y;
    As[0][c4 + 2][row] = a.z;  As[0][c4 + 3][row] = a.w;
    Bs[0][c4 + 0][row] = bb.x; Bs[0][c4 + 1][row] = bb.y;
    Bs[0][c4 + 2][row] = bb.z; Bs[0][c4 + 3][row] = bb.w;
    __syncthreads();

    float acc[8][8];
#pragma unroll
    for (int i = 0; i < 8; i++)
#pragma unroll
        for (int j = 0; j < 8; j++) acc[i][j] = 0.f;

    int ktiles = K >> 3;
    int buf = 0;
    for (int kt = 0; kt < ktiles; kt++) {
        if (kt + 1 < ktiles) {
            a  = *(const float4*)(Aptr + (size_t)(kt + 1) * 8);
            bb = *(const float4*)(Bptr + (size_t)(kt + 1) * 8);
        }
#pragma unroll
        for (int k = 0; k < 8; k++) {
            float ar[8], br[8];
            *(float4*)(ar)     = *(const float4*)&As[buf][k][ty * 8];
            *(float4*)(ar + 4) = *(const float4*)&As[buf][k][ty * 8 + 4];
            *(float4*)(br)     = *(const float4*)&Bs[buf][k][tx * 8];
            *(float4*)(br + 4) = *(const float4*)&Bs[buf][k][tx * 8 + 4];
#pragma unroll
            for (int i = 0; i < 8; i++)
#pragma unroll
                for (int j = 0; j < 8; j++)
                    acc[i][j] = fmaf(ar[i], br[j], acc[i][j]);
        }
        if (kt + 1 < ktiles) {
            int nb = buf ^ 1;
            As[nb][c4 + 0][row] = a.x;  As[nb][c4 + 1][row] = a.y;
            As[nb][c4 + 2][row] = a.z;  As[nb][c4 + 3][row] = a.w;
            Bs[nb][c4 + 0][row] = bb.x; Bs[nb][c4 + 1][row] = bb.y;
            Bs[nb][c4 + 2][row] = bb.z; Bs[nb][c4 + 3][row] = bb.w;
            __syncthreads();
            buf = nb;
        }
    }

    float bsv[8];
#pragma unroll
    for (int j = 0; j < 8; j++) bsv[j] = bias[n0 + tx * 8 + j];
#pragma unroll
    for (int i = 0; i < 8; i++) {
        int m = m0 + ty * 8 + i;
        float4 v0, v1;
        v0.x = acc[i][0] + bsv[0]; v0.y = acc[i][1] + bsv[1];
        v0.z = acc[i][2] + bsv[2]; v0.w = acc[i][3] + bsv[3];
        v1.x = acc[i][4] + bsv[4]; v1.y = acc[i][5] + bsv[5];
        v1.z = acc[i][6] + bsv[6]; v1.w = acc[i][7] + bsv[7];
        *(float4*)(C + (size_t)m * N + n0 + tx * 8)     = v0;
        *(float4*)(C + (size_t)m * N + n0 + tx * 8 + 4) = v1;
    }
}

// ---------------- persistent bidirectional LSTM recurrence ----------------
__device__ __forceinline__ float fsig(float x) {
    return __fdividef(1.f, 1.f + __expf(-x));
}
__device__ __forceinline__ float ftanh_(float x) {
    return 2.f * __fdividef(1.f, 1.f + __expf(-2.f * x)) - 1.f;
}

// grid = 128 CTAs (64 per direction), 256 threads (8 warps -> 8 h-outputs).
// Whh weights register-resident; h broadcast through L2 via hout rows;
// step barrier = counting release-add / per-thread acquire poll.
__global__ __launch_bounds__(256, 1) void lstm_rec(
    const float* __restrict__ Whh2,   // [2][2048][512]
    const float* __restrict__ xp2,    // [2][L][2048]
    float* hout, int cbase)           // [L][1024]
{
    int dir   = blockIdx.x >> 6;
    int b     = blockIdx.x & 63;
    int tid   = threadIdx.x;
    int j     = tid >> 5;
    int lane  = tid & 31;
    int hglob = b * 8 + j;
    int hcol  = dir * HDIR + hglob;
    int* cnt  = &g_cnt[cbase + dir * 32];

    const float* W  = Whh2 + (size_t)dir * G4 * HDIR;
    const float* xp = xp2  + (size_t)dir * LSEQ * G4;

    float w[4][16];
#pragma unroll
    for (int q = 0; q < 4; q++) {
        const float* wr = W + (size_t)(q * HDIR + hglob) * HDIR;
#pragma unroll
        for (int i = 0; i < 16; i++) w[q][i] = wr[lane + 32 * i];
    }

    float c = 0.f;

    for (int s = 0; s < LSEQ; ++s) {
        int t = dir ? (LSEQ - 1 - s) : s;

        // xp prefetch (independent of the step barrier)
        float xpv = 0.f;
        if (lane < 4) xpv = __ldg(xp + (size_t)t * G4 + lane * HDIR + hglob);

        float hreg[16];
        if (s == 0) {
#pragma unroll
            for (int i = 0; i < 16; i++) hreg[i] = 0.f;
        } else {
            int target = s * NCD, v;
            do {
                asm volatile("ld.acquire.gpu.global.s32 %0, [%1];"
                             : "=r"(v) : "l"(cnt));
            } while (v < target);
            int tp = dir ? (t + 1) : (t - 1);
            const float* hp = hout + (size_t)tp * HID + dir * HDIR + lane;
#pragma unroll
            for (int i = 0; i < 16; i++) hreg[i] = __ldcg(hp + 32 * i);
        }

        float s0 = 0.f, s1 = 0.f, s2 = 0.f, s3 = 0.f;
#pragma unroll
        for (int i = 0; i < 16; i++) {
            s0 = fmaf(w[0][i], hreg[i], s0);
            s1 = fmaf(w[1][i], hreg[i], s1);
            s2 = fmaf(w[2][i], hreg[i], s2);
            s3 = fmaf(w[3][i], hreg[i], s3);
        }
#pragma unroll
        for (int off = 16; off; off >>= 1) {
            s0 += __shfl_xor_sync(0xffffffffu, s0, off);
            s1 += __shfl_xor_sync(0xffffffffu, s1, off);
            s2 += __shfl_xor_sync(0xffffffffu, s2, off);
            s3 += __shfl_xor_sync(0xffffffffu, s3, off);
        }
        float x0 = __shfl_sync(0xffffffffu, xpv, 0);
        float x1 = __shfl_sync(0xffffffffu, xpv, 1);
        float x2 = __shfl_sync(0xffffffffu, xpv, 2);
        float x3 = __shfl_sync(0xffffffffu, xpv, 3);

        if (lane == 0) {
            float gi = fsig(s0 + x0);
            float gf = fsig(s1 + x1);
            float gg = ftanh_(s2 + x2);
            float go = fsig(s3 + x3);
            c = gf * c + gi * gg;
            hout[(size_t)t * HID + hcol] = go * ftanh_(c);
        }
        __syncthreads();     // all 8 h writes of this CTA done before publish
        if (tid == 0) {
            int one = 1;
            asm volatile("red.release.gpu.global.add.s32 [%0], %1;"
                         :: "l"(cnt), "r"(one) : "memory");
        }
    }
}

// ---------------- score epilogue ------------------------------------------
__global__ void score_reduce(const float* __restrict__ wo) {
    int t = blockIdx.x, tid = threadIdx.x;
    float a0 = 0.f, a1 = 0.f;
    for (int jj = tid; jj < 512; jj += 256) {
        a0 += wo[jj]       * tanhf(g_feat[(size_t)t * 512 + jj]);
        a1 += wo[512 + jj] * tanhf(g_feat[(size_t)LSEQ * 512 + (size_t)t * 512 + jj]);
    }
#pragma unroll
    for (int off = 16; off; off >>= 1) {
        a0 += __shfl_xor_sync(0xffffffffu, a0, off);
        a1 += __shfl_xor_sync(0xffffffffu, a1, off);
    }
    __shared__ float r0[8], r1[8];
    if ((tid & 31) == 0) { r0[tid >> 5] = a0; r1[tid >> 5] = a1; }
    __syncthreads();
    if (tid == 0) {
        float t0 = 0.f, t1 = 0.f;
#pragma unroll
        for (int i = 0; i < 8; i++) { t0 += r0[i]; t1 += r1[i]; }
        g_s[t] = t0;           // s_head
        g_s[LSEQ + t] = t1;    // s_modif
    }
}

__global__ void score_out(float* __restrict__ out, const float* __restrict__ bo) {
    int m = blockIdx.x;
    float base = g_s[LSEQ + m] + bo[0];
    for (int h = threadIdx.x; h < LSEQ; h += blockDim.x)
        out[(size_t)m * LSEQ + h] = base + g_s[h];
}

// ---------------- launch ---------------------------------------------------
extern "C" void kernel_launch(void* const* d_in, const int* in_sizes, int n_in,
                              void* d_out, int out_size) {
    const int*   wt   = (const int*)d_in[0];
    const int*   pt   = (const int*)d_in[1];
    const float* wemb = (const float*)d_in[2];
    const float* pemb = (const float*)d_in[3];
    const float* Wih0 = (const float*)d_in[4];
    const float* Whh0 = (const float*)d_in[5];
    const float* b0   = (const float*)d_in[6];
    const float* Wih1 = (const float*)d_in[7];
    const float* Whh1 = (const float*)d_in[8];
    const float* b1   = (const float*)d_in[9];
    const float* Wh   = (const float*)d_in[10];
    const float* bh   = (const float*)d_in[11];
    const float* Wm   = (const float*)d_in[12];
    const float* bm   = (const float*)d_in[13];
    const float* wo   = (const float*)d_in[14];
    const float* bo   = (const float*)d_in[15];
    float* out = (float*)d_out;

    float *p_emb, *p_xp, *p_h0, *p_h1, *p_feat;
    cudaGetSymbolAddress((void**)&p_emb,  g_emb);
    cudaGetSymbolAddress((void**)&p_xp,   g_xp);
    cudaGetSymbolAddress((void**)&p_h0,   g_h0);
    cudaGetSymbolAddress((void**)&p_h1,   g_h1);
    cudaGetSymbolAddress((void**)&p_feat, g_feat);

    embed_kernel<<<LSEQ, 128>>>(wt, pt, wemb, pemb);

    // layer 0 input projections: [1024,400] @ [2048,400]^T, both directions
    gemm128<<<dim3(G4 / 128, LSEQ / 128, 2), 256>>>(
        p_emb, Wih0, b0, p_xp,
        Wih0 + (size_t)G4 * DIN0, b0 + G4, p_xp + (size_t)LSEQ * G4,
        LSEQ, G4, DIN0);
    lstm_rec<<<128, 256>>>(Whh0, p_xp, p_h0, 0);

    // layer 1 input projections: [1024,1024] @ [2048,1024]^T, both directions
    gemm128<<<dim3(G4 / 128, LSEQ / 128, 2), 256>>>(
        p_h0, Wih1, b1, p_xp,
        Wih1 + (size_t)G4 * HID, b1 + G4, p_xp + (size_t)LSEQ * G4,
        LSEQ, G4, HID);
    lstm_rec<<<128, 256>>>(Whh1, p_xp, p_h1, 64);

    // head/modifier features: [1024,1024] @ [512,1024]^T (z: Wh / Wm)
    gemm128<<<dim3(512 / 128, LSEQ / 128, 2), 256>>>(
        p_h1, Wh, bh, p_feat,
        Wm, bm, p_feat + (size_t)LSEQ * 512,
        LSEQ, 512, HID);

    score_reduce<<<LSEQ, 256>>>(wo);
    score_out<<<LSEQ, 256>>>(out, bo);
}